// round 9
// baseline (speedup 1.0000x reference)
#include <cuda_runtime.h>
#include <cuda_bf16.h>
#include <cstdint>
#include <math.h>

// ---------------------------------------------------------------------------
// Problem constants
// ---------------------------------------------------------------------------
#define NB    16
#define CIN   128
#define COUT  128
#define HDIM  56
#define WDIM  56
#define LPIX  3136
#define PADW  58
#define PADSZ 3364
#define MTOT  50176                 // 392 tiles of 128
#define KTOT  1152
#define NCH   72                    // k16 chunks
#define TILES 392
#define TH_FIX 2.0e-3f
#define LISTCAP (1 << 20)

#define PI_F      3.14159265358979323846f
#define HALFPI_F  1.57079632679489661923f
#define INVPI_F   0.31830988618379067154f

// ---------------------------------------------------------------------------
// Device scratch (static -- no allocations allowed)
// ---------------------------------------------------------------------------
__device__ __align__(16) __nv_bfloat16 g_xh[(size_t)NB * PADSZ * CIN];   // 13.8MB
__device__ __align__(16) __nv_bfloat16 g_xl[(size_t)NB * PADSZ * CIN];   // 13.8MB
__device__ __align__(16) float         g_xpf[(size_t)NB * PADSZ * CIN];  // 27.6MB
__device__ __align__(16) __nv_bfloat16 g_Bh[NCH * 256 * 16];             // 576KB
__device__ __align__(16) __nv_bfloat16 g_Bl[NCH * 256 * 16];
__device__ __align__(16) float         g_Wc[9 * COUT * CIN];             // 576KB
__device__ __align__(16) float         g_Ws[9 * COUT * CIN];
__device__ unsigned int g_cnt;
__device__ unsigned int g_list[LISTCAP];

// tap offsets in channel-last padded layout (elements)
__constant__ int c_koff[9] = {0, 128, 256,
                              58 * 128, 59 * 128, 60 * 128,
                              116 * 128, 117 * 128, 118 * 128};

// ---------------------------------------------------------------------------
// PTX helpers (generic sm_80-level only -- NO tcgen05 / NO 'a'-features)
// ---------------------------------------------------------------------------
__device__ __forceinline__ uint32_t smem_u32(const void* p) {
    uint32_t a;
    asm("{ .reg .u64 t; cvta.to.shared.u64 t, %1; cvt.u32.u64 %0, t; }"
        : "=r"(a) : "l"(p));
    return a;
}
#define CP16(dst_u32, src_ptr) \
    asm volatile("cp.async.cg.shared.global [%0], [%1], 16;" \
                 :: "r"(dst_u32), "l"(src_ptr) : "memory")
#define CP_COMMIT() asm volatile("cp.async.commit_group;" ::: "memory")
#define CP_WAIT1()  asm volatile("cp.async.wait_group 1;" ::: "memory")

#define LDSM4(R, addr) \
    asm volatile("ldmatrix.sync.aligned.m8n8.x4.shared.b16 {%0,%1,%2,%3}, [%4];" \
                 : "=r"((R)[0]), "=r"((R)[1]), "=r"((R)[2]), "=r"((R)[3]) \
                 : "r"(addr))

#define MMA_BF16(C, A, B0, B1) \
    asm volatile("mma.sync.aligned.m16n8k16.row.col.f32.bf16.bf16.f32 " \
                 "{%0,%1,%2,%3}, {%4,%5,%6,%7}, {%8,%9}, {%0,%1,%2,%3};" \
                 : "+f"((C)[0]), "+f"((C)[1]), "+f"((C)[2]), "+f"((C)[3]) \
                 : "r"((A)[0]), "r"((A)[1]), "r"((A)[2]), "r"((A)[3]), \
                   "r"(B0), "r"(B1))

// smem swizzle for 32B rows: off = r*32 + h*16, XOR bit4 with r-bit2
__device__ __forceinline__ uint32_t swz(int r, int h) {
    return (uint32_t)((r * 32 + h * 16) ^ ((r & 4) << 2));
}

// ---------------------------------------------------------------------------
// Shared epilogue math (identical to the passing fp32 kernel)
// ---------------------------------------------------------------------------
__device__ __forceinline__ void phase_epilogue(float a, float bb, float bv,
                                               float* oval, float* tval) {
    bool a_gt = a > 0.0f;
    bool b_gt = bb > 0.0f;
    bool eq   = (a_gt == b_gt);
    float theta = eq ? atanf(bb / (a + 1e-5f)) : -atanf(a / (bb + 1e-5f));
    float peak  = eq ? (a_gt ? HALFPI_F : -HALFPI_F) : (b_gt ? 0.0f : -PI_F);
    theta = peak - theta;
    float st, ct;
    sincosf(theta, &st, &ct);
    *oval = fmaf(st, a, ct * bb) + bv;
    *tval = theta * INVPI_F;
}

// ---------------------------------------------------------------------------
// Prep 1: pad + transpose to channel-last + bf16 hi/lo split + fp32 copy
// ---------------------------------------------------------------------------
__global__ void padsplit_kernel(const float* __restrict__ x) {
    __shared__ float tile[CIN][WDIM];
    const int b  = blockIdx.x / PADW;
    const int yy = blockIdx.x % PADW;
    const int ysrc = yy - 1;
    const bool rowvalid = (ysrc >= 0) && (ysrc < HDIM);
    const int tid = threadIdx.x;
    if (blockIdx.x == 0 && tid == 0) g_cnt = 0;   // reset fixup list each launch

    if (rowvalid) {
        for (int i = tid; i < CIN * WDIM; i += 256) {
            int c = i / WDIM, xx = i % WDIM;
            tile[c][xx] = x[((size_t)(b * CIN + c) * HDIM + ysrc) * WDIM + xx];
        }
    }
    __syncthreads();

    for (int i = tid; i < PADW * CIN; i += 256) {
        int xx = i / CIN, c = i % CIN;
        float v = 0.0f;
        if (rowvalid && xx >= 1 && xx <= WDIM) v = tile[c][xx - 1];
        __nv_bfloat16 vh = __float2bfloat16(v);
        __nv_bfloat16 vl = __float2bfloat16(v - __bfloat162float(vh));
        size_t oidx = ((size_t)b * PADSZ + yy * PADW + xx) * CIN + c;
        g_xh[oidx]  = vh;
        g_xl[oidx]  = vl;
        g_xpf[oidx] = v;
    }
}

// ---------------------------------------------------------------------------
// Prep 2: fold cos/sin into weights; bf16 split chunked B tiles + fp32 copies
// index space: [kc(72)][n(256)][kl(16)]
// ---------------------------------------------------------------------------
__global__ void wsplit_kernel(const float* __restrict__ weight,
                              const float* __restrict__ b_k) {
    int idx = blockIdx.x * 256 + threadIdx.x;
    int kl = idx & 15;
    int n  = (idx >> 4) & 255;
    int kc = idx >> 12;
    int kk = kc * 16 + kl;
    int kp = kk >> 7, c = kk & 127;
    int o = n >> 1, s = n & 1;
    float bkv = b_k[kp * COUT + o];
    float w   = weight[(kp * COUT + o) * CIN + c];
    float tr  = s ? sinf(bkv) : cosf(bkv);
    float full = w * tr;
    __nv_bfloat16 wh = __float2bfloat16(full);
    __nv_bfloat16 wl = __float2bfloat16(full - __bfloat162float(wh));
    g_Bh[idx] = wh;         // idx == (kc*256 + n)*16 + kl  (layout by construction)
    g_Bl[idx] = wl;
    if (s == 0) g_Wc[(kp * COUT + o) * CIN + c] = full;
    else        g_Ws[(kp * COUT + o) * CIN + c] = full;
}

// ---------------------------------------------------------------------------
// Main: HMMA (mma.sync bf16) implicit-GEMM, 3-term split, fused epilogue
// grid (392, 2), 256 threads, 48KB static smem, 3-stage cp.async pipeline
// ---------------------------------------------------------------------------
#define STAGE_BYTES 16384
#define AH_O 0
#define AL_O 4096
#define BH_O 8192
#define BL_O 12288

__global__ void __launch_bounds__(256, 1)
conv_hmma(const float* __restrict__ bias, float* __restrict__ out) {
    __shared__ __align__(128) char sm[3 * STAGE_BYTES];
    const int tid  = threadIdx.x;
    const int wid  = tid >> 5;
    const int lane = tid & 31;
    const int tile = blockIdx.x;
    const int n0   = blockIdx.y * 128;

    const uint32_t smbase = smem_u32(sm);

    // ---- cp.async assignments: thread t handles row t>>1, half t&1 ----
    const int rA = tid >> 1, hA = tid & 1;
    const int m  = tile * 128 + rA;
    const int bi = m / LPIX;
    const int li = m - bi * LPIX;
    const int yi = li / WDIM;
    const int xi = li - yi * WDIM;
    const size_t prow = ((size_t)bi * PADSZ + yi * PADW + xi) * CIN;
    const uint32_t sOff = swz(rA, hA);
    const int nB = n0 + rA;              // B row (n_local = rA)

    // ---- warp tiling: 2 (m) x 4 (n); warp tile 64x32 ----
    const int wm = wid & 1;
    const int wn = wid >> 1;

    // ldmatrix lane offsets (row-local within the 128-row tile)
    const int rowa = wm * 64 + (lane & 15);
    const int rowb = wn * 32 + (lane & 15);
    const int lh   = lane >> 4;
    const uint32_t offA = swz(rowa, lh);     // +ma*512 for ma-th 16-row group
    const uint32_t offB = swz(rowb, lh);     // +nb*512

    float acc[4][4][4];
#pragma unroll
    for (int i = 0; i < 4; i++)
#pragma unroll
        for (int j = 0; j < 4; j++)
#pragma unroll
            for (int k = 0; k < 4; k++) acc[i][j][k] = 0.0f;

    auto issue = [&](int kc, int s) {
        const uint32_t st = smbase + s * STAGE_BYTES;
        const int kp = kc >> 3, cb = (kc & 7) << 4;
        const size_t ga = prow + c_koff[kp] + cb + hA * 8;
        CP16(st + AH_O + sOff, g_xh + ga);
        CP16(st + AL_O + sOff, g_xl + ga);
        const size_t gb = ((size_t)kc * 256 + nB) * 16 + hA * 8;
        CP16(st + BH_O + sOff, g_Bh + gb);
        CP16(st + BL_O + sOff, g_Bl + gb);
    };

    // ---- pipeline prologue ----
    issue(0, 0); CP_COMMIT();
    issue(1, 1); CP_COMMIT();

    for (int kc = 0; kc < NCH; kc++) {
        CP_WAIT1();
        __syncthreads();
        if (kc + 2 < NCH) { issue(kc + 2, (kc + 2) % 3); }
        CP_COMMIT();     // empty group when no issue -> uniform group counting

        const uint32_t st = smbase + (kc % 3) * STAGE_BYTES;

        uint32_t ah[4][4], al[4][4], bh[2][4], bl[2][4];
#pragma unroll
        for (int ma = 0; ma < 4; ma++) {
            LDSM4(ah[ma], st + AH_O + offA + ma * 512);
            LDSM4(al[ma], st + AL_O + offA + ma * 512);
        }
#pragma unroll
        for (int nb = 0; nb < 2; nb++) {
            LDSM4(bh[nb], st + BH_O + offB + nb * 512);
            LDSM4(bl[nb], st + BL_O + offB + nb * 512);
        }

#pragma unroll
        for (int ma = 0; ma < 4; ma++)
#pragma unroll
            for (int nb = 0; nb < 2; nb++)
#pragma unroll
                for (int j = 0; j < 2; j++) {
                    const int na = nb * 2 + j;
                    MMA_BF16(acc[ma][na], ah[ma], bh[nb][j], bh[nb][j + 2]);
                    MMA_BF16(acc[ma][na], al[ma], bh[nb][j], bh[nb][j + 2]);
                    MMA_BF16(acc[ma][na], ah[ma], bl[nb][j], bl[nb][j + 2]);
                }
    }

    // ---- epilogue: lane-local (a,bb) pairs ----
    const int q  = lane >> 2;      // row within atom
    const int cp = lane & 3;       // channel sub-index
#pragma unroll
    for (int ma = 0; ma < 4; ma++) {
#pragma unroll
        for (int rh = 0; rh < 2; rh++) {
            const int mloc = wm * 64 + ma * 16 + rh * 8 + q;
            const int mg = tile * 128 + mloc;
            const int b  = mg / LPIX;
            const int l  = mg - b * LPIX;
            float* ob = out + (size_t)b * 256 * LPIX + l;
#pragma unroll
            for (int na = 0; na < 4; na++) {
                const float a  = acc[ma][na][rh * 2];
                const float bb = acc[ma][na][rh * 2 + 1];
                const int o = (n0 >> 1) + wn * 16 + na * 4 + cp;
                float oval, tval;
                phase_epilogue(a, bb, bias[o], &oval, &tval);
                ob[(size_t)o * LPIX]         = oval;
                ob[(size_t)(o + 128) * LPIX] = tval;
                if (fabsf(a) < TH_FIX || fabsf(bb) < TH_FIX) {
                    unsigned u = atomicAdd(&g_cnt, 1u);
                    if (u < LISTCAP)
                        g_list[u] = ((unsigned)mg << 8) | (unsigned)o;
                }
            }
        }
    }
}

// ---------------------------------------------------------------------------
// Fixup: exact fp32 recompute of flagged (near-discontinuity) elements.
// One warp per element; lanes split the 128 channels.
// ---------------------------------------------------------------------------
__global__ void fixup_kernel(const float* __restrict__ bias,
                             float* __restrict__ out) {
    const unsigned gw   = blockIdx.x * 8 + (threadIdx.x >> 5);
    const int lane      = threadIdx.x & 31;
    unsigned cnt = g_cnt;
    if (cnt > LISTCAP) cnt = LISTCAP;
    const unsigned stride = gridDim.x * 8;

    for (unsigned idx = gw; idx < cnt; idx += stride) {
        const unsigned e = g_list[idx];
        const int o  = (int)(e & 255u);
        const int mg = (int)(e >> 8);
        const int b = mg / LPIX;
        const int l = mg - b * LPIX;
        const int y = l / WDIM;
        const int x = l - y * WDIM;
        const float* xb = g_xpf + ((size_t)b * PADSZ + y * PADW + x) * CIN;

        float a = 0.0f, bb = 0.0f;
#pragma unroll
        for (int kp = 0; kp < 9; kp++) {
            const float4 xv = ((const float4*)(xb + c_koff[kp]))[lane];
            const float4 wc = ((const float4*)(g_Wc + (kp * COUT + o) * CIN))[lane];
            const float4 ws = ((const float4*)(g_Ws + (kp * COUT + o) * CIN))[lane];
            a  += xv.x * wc.x + xv.y * wc.y + xv.z * wc.z + xv.w * wc.w;
            bb += xv.x * ws.x + xv.y * ws.y + xv.z * ws.z + xv.w * ws.w;
        }
#pragma unroll
        for (int s = 16; s; s >>= 1) {
            a  += __shfl_xor_sync(0xFFFFFFFFu, a, s);
            bb += __shfl_xor_sync(0xFFFFFFFFu, bb, s);
        }
        if (lane == 0) {
            float oval, tval;
            phase_epilogue(a, bb, bias[o], &oval, &tval);
            float* ob = out + (size_t)b * 256 * LPIX + l;
            ob[(size_t)o * LPIX]         = oval;
            ob[(size_t)(o + 128) * LPIX] = tval;
        }
    }
}

// ---------------------------------------------------------------------------
// Launch (inputs: x, weight, b_k, bias)
// ---------------------------------------------------------------------------
extern "C" void kernel_launch(void* const* d_in, const int* in_sizes, int n_in,
                              void* d_out, int out_size) {
    const float* x      = (const float*)d_in[0];
    const float* weight = (const float*)d_in[1];
    const float* b_k    = (const float*)d_in[2];
    const float* bias   = (const float*)d_in[3];
    float* out          = (float*)d_out;

    padsplit_kernel<<<NB * PADW, 256>>>(x);
    wsplit_kernel<<<(NCH * 256 * 16) / 256, 256>>>(weight, b_k);
    dim3 grid(TILES, 2);
    conv_hmma<<<grid, 256>>>(bias, out);
    fixup_kernel<<<296, 256>>>(bias, out);
}